// round 8
// baseline (speedup 1.0000x reference)
#include <cuda_runtime.h>
#include <cfloat>
#include <math.h>

// ---------------- problem constants ----------------
#define NN   100000   // nodes
#define NE   800000   // edges
#define NC   20000    // clusters
#define NGE  320000   // global edges
#define NG   256      // graphs
#define EPSB 1e-5f
#define NSEG (NN + NC)
#define NEALL (NE + NGE)
#define SLOT8 8
#define SQOFF (256 * SLOT8)
#define LSTRIDE (512 * SLOT8)
#define CNT_BYTES (NSEG * 4)
#define ZERO_BYTES (CNT_BYTES + 2 * LSTRIDE * 8)
#define TBLK 4375                    // NEALL/256 exactly

// ---------------- scratch (device globals) ----------------
__device__ __align__(16) float  g_agg[NC * 96];
__device__ __align__(16) float  g_h1[NN * 80];
__device__ __align__(16) float  g_h2[NN * 96];
__device__ __align__(16) float  g_y [NC * 96];
__device__ __align__(16) float  g_y2[NC * 256];
__device__ __align__(16) unsigned char g_zerobuf[ZERO_BYTES];   // [cnt | stats]
__device__ __align__(16) int    g_rowptr[NSEG + 1];
__device__ __align__(16) int    g_cur[NSEG];
__device__ __align__(16) int    g_colidx[NEALL];
__device__ int    g_nstart[NC + 1];
__device__ int    g_gstart[NG + 1];
__device__ int    g_ybatch[NC];
__device__ int    g_psum[128];
__device__ __align__(16) float  g_scale[256];
__device__ __align__(16) float  g_shift[256];

// ---------------- tf32 / mma helpers ----------------
__device__ __forceinline__ unsigned tf32cvt(float f) {
    unsigned u;
    asm("cvt.rna.tf32.f32 %0, %1;" : "=r"(u) : "f"(f));
    return u;
}
__device__ __forceinline__ void mma_tf32(float4& d, uint2 a01, uint2 a23, uint2 b) {
    asm volatile(
        "mma.sync.aligned.m16n8k8.row.col.f32.tf32.tf32.f32 "
        "{%0,%1,%2,%3}, {%4,%5,%6,%7}, {%8,%9}, {%0,%1,%2,%3};"
        : "+f"(d.x), "+f"(d.y), "+f"(d.z), "+f"(d.w)
        : "r"(a01.x), "r"(a01.y), "r"(a23.x), "r"(a23.y), "r"(b.x), "r"(b.y));
}

// ---------------- CSR build ----------------
__global__ void k_hist(const int* __restrict__ ei, const int* __restrict__ gei,
                       int* __restrict__ cnt) {
    int i = blockIdx.x * blockDim.x + threadIdx.x;
    if (i < NE) atomicAdd(&cnt[ei[NE + i]], 1);
    else if (i < NEALL) atomicAdd(&cnt[NN + gei[NGE + (i - NE)]], 1);
}

__global__ void k_scan1(const int* __restrict__ cnt, int* __restrict__ loc,
                        int* __restrict__ psum, int n) {
    __shared__ int sh[256];
    int t = threadIdx.x;
    int idx = blockIdx.x * 1024 + t * 4;
    int a0 = 0, a1 = 0, a2 = 0, a3 = 0;
    if (idx + 3 < n) {
        int4 q = *reinterpret_cast<const int4*>(cnt + idx);
        a0 = q.x; a1 = q.y; a2 = q.z; a3 = q.w;
    } else {
        if (idx     < n) a0 = cnt[idx];
        if (idx + 1 < n) a1 = cnt[idx + 1];
        if (idx + 2 < n) a2 = cnt[idx + 2];
    }
    int s = a0 + a1 + a2 + a3;
    sh[t] = s; __syncthreads();
    for (int off = 1; off < 256; off <<= 1) {
        int u = (t >= off) ? sh[t - off] : 0;
        __syncthreads(); sh[t] += u; __syncthreads();
    }
    int excl = sh[t] - s;
    if (idx     < n) loc[idx]     = excl;
    if (idx + 1 < n) loc[idx + 1] = excl + a0;
    if (idx + 2 < n) loc[idx + 2] = excl + a0 + a1;
    if (idx + 3 < n) loc[idx + 3] = excl + a0 + a1 + a2;
    if (t == 255) psum[blockIdx.x] = sh[t];
}

// scan3 with embedded top-level scan (each block redundantly scans psum)
__global__ void k_scan3f(int* __restrict__ rowptr, int* __restrict__ cur,
                         const int* __restrict__ psum, int n, int total, int nb) {
    __shared__ int sh[128];
    __shared__ int excl[128];
    int t = threadIdx.x;
    int v = 0;
    if (t < 128) { v = (t < nb) ? psum[t] : 0; sh[t] = v; }
    __syncthreads();
    for (int off = 1; off < 128; off <<= 1) {
        int u = 0;
        if (t < 128 && t >= off) u = sh[t - off];
        __syncthreads();
        if (t < 128) sh[t] += u;
        __syncthreads();
    }
    if (t < 128) excl[t] = sh[t] - v;
    __syncthreads();
    int i = blockIdx.x * blockDim.x + t;
    if (i < n) {
        int val = rowptr[i] + excl[i >> 10];
        rowptr[i] = val;
        cur[i] = val;
    }
    if (i == 0) rowptr[n] = total;
}

// ticket fill + (fused) cluster segment boundaries
__global__ void k_ticket_bound(const int* __restrict__ ei, const int* __restrict__ gei,
                               int* __restrict__ cur, int* __restrict__ colidx,
                               const int* __restrict__ cluster, int* __restrict__ nstart) {
    int b = blockIdx.x, t = threadIdx.x;
    if (b < TBLK) {
        int i = b * 256 + t;
        if (i < NE) {
            int p = atomicAdd(&cur[ei[NE + i]], 1);
            colidx[p] = ei[i];
        } else if (i < NEALL) {
            int e = i - NE;
            int p = atomicAdd(&cur[NN + gei[NGE + e]], 1);
            colidx[p] = gei[e];
        }
    } else {
        int i = (b - TBLK) * 256 + t;
        if (i == 0) { nstart[0] = 0; nstart[NC] = NN; }
        else if (i < NN) {
            int c0 = cluster[i - 1], c1 = cluster[i];
            for (int c = c0 + 1; c <= c1; ++c) nstart[c] = i;
        }
    }
}

// ---------------- cluster gather (layer 3 only) ----------------
__global__ void k_gather96(const int* __restrict__ rowptr, const int* __restrict__ colidx,
                           const float* __restrict__ src, float* __restrict__ agg, int N) {
    int w = (blockIdx.x * blockDim.x + threadIdx.x) >> 5;
    int lane = threadIdx.x & 31;
    if (w >= N) return;
    int s0 = rowptr[w], s1 = rowptr[w + 1];
    const float4* s4 = reinterpret_cast<const float4*>(src);
    float4 acc = make_float4(0.f, 0.f, 0.f, 0.f);
    bool act = lane < 24;
    int e = s0;
    for (; e + 3 < s1; e += 4) {
        int i0 = colidx[e] * 24,     i1 = colidx[e + 1] * 24;
        int i2 = colidx[e + 2] * 24, i3 = colidx[e + 3] * 24;
        if (act) {
            float4 v0 = s4[i0 + lane], v1 = s4[i1 + lane];
            float4 v2 = s4[i2 + lane], v3 = s4[i3 + lane];
            acc.x += (v0.x + v1.x) + (v2.x + v3.x);
            acc.y += (v0.y + v1.y) + (v2.y + v3.y);
            acc.z += (v0.z + v1.z) + (v2.z + v3.z);
            acc.w += (v0.w + v1.w) + (v2.w + v3.w);
        }
    }
    for (; e < s1; ++e) {
        if (act) {
            float4 v = s4[colidx[e] * 24 + lane];
            acc.x += v.x; acc.y += v.y; acc.z += v.z; acc.w += v.w;
        }
    }
    if (act) reinterpret_cast<float4*>(agg)[w * 24 + lane] = acc;
}

// ---------------- segment boundaries ----------------
__global__ void k_bound(const int* __restrict__ seg, int n, int nseg,
                        int* __restrict__ start) {
    int i = blockIdx.x * blockDim.x + threadIdx.x;
    if (i == 0) { start[0] = 0; start[nseg] = n; }
    else if (i < n) {
        int c0 = seg[i - 1], c1 = seg[i];
        for (int c = c0 + 1; c <= c1; ++c) start[c] = i;
    }
}

// cluster pool with BN2 fold (sign-safe)
__global__ void __launch_bounds__(128)
k_pool(const float* __restrict__ h2, const int* __restrict__ nstart,
       const int* __restrict__ batch, const float* __restrict__ scale,
       const float* __restrict__ shift, float* __restrict__ y, int* __restrict__ ybatch) {
    int c = blockIdx.x;
    int t = threadIdx.x;
    int ns = nstart[c], ne = nstart[c + 1];
    if (t < 96) {
        float mx = -FLT_MAX, mn = FLT_MAX;
        for (int n = ns; n < ne; ++n) {
            float v = h2[(size_t)n * 96 + t];
            mx = fmaxf(mx, v); mn = fminf(mn, v);
        }
        float sc = scale[t];
        y[(size_t)c * 96 + t] = fmaf(sc >= 0.f ? mx : mn, sc, shift[t]);
    } else if (t == 96 && ne > ns) {
        ybatch[c] = batch[ne - 1];
    }
}

__global__ void __launch_bounds__(256)
k_final(const float* __restrict__ y2, const int* __restrict__ gstart,
        float* __restrict__ out) {
    int g = blockIdx.x;
    int f = threadIdx.x;
    int gs = gstart[g], ge = gstart[g + 1];
    float mx = -FLT_MAX;
    for (int c = gs; c < ge; ++c)
        mx = fmaxf(mx, y2[(size_t)c * 256 + f]);
    out[(size_t)g * 256 + f] = mx;
}

// ---------------- FUSED gather + TF32 GEMM (+relu, +BN stats) ----------------
// MODE 1: layer 1 — gather emb[x[src]]; h-half = emb[x[node]].
// MODE 2: layer 2 — BN1 computed in-prologue from statsIn; gather BN1(h1[src]);
//                   h-half = BN1(h1[node]).
template <int K, int DAGG, int DH, int MTOT, int MCHUNK, int MODE>
__global__ void __launch_bounds__(256, 2)
k_gemm_fused(const int* __restrict__ rowptr, const int* __restrict__ colidx,
             const int* __restrict__ x, const float* __restrict__ emb,
             const float* __restrict__ h, const double* __restrict__ statsIn,
             const float* __restrict__ gamma, const float* __restrict__ beta,
             const float* __restrict__ W, const float* __restrict__ bias,
             float* __restrict__ out, int N, double* __restrict__ statsOut) {
    constexpr int NK = K / 32, NSPAN = MCHUNK / 2, NT = NSPAN / 8;
    constexpr int ZS = 136, WS = 40, A4 = DAGG / 4;
    extern __shared__ __align__(16) unsigned char smraw[];
    unsigned* z_s  = reinterpret_cast<unsigned*>(smraw);         // 32*ZS
    unsigned* w_s  = z_s + 32 * ZS;                              // MCHUNK*WS
    float*    agg_s = reinterpret_cast<float*>(w_s + MCHUNK * WS); // 128*DAGG
    float*    sc_s = agg_s + 128 * DAGG;                         // DH (MODE2)
    float*    sh_s = sc_s + DH;
    int*      xs_s = reinterpret_cast<int*>(sc_s);               // 128 (MODE1)

    const int t = threadIdx.x, lane = t & 31, wid = t >> 5;
    const int wm = wid & 3, wn = wid >> 2, gr = lane >> 2, tc = lane & 3;
    const int nbase = blockIdx.x * 128, cbase = blockIdx.y * MCHUNK;

    // ---- prologue: BN1 params (MODE2) or x cache (MODE1) ----
    if (MODE == 2) {
        if (t < DH) {
            double s = 0.0, s2 = 0.0;
#pragma unroll
            for (int k2 = 0; k2 < SLOT8; ++k2) {
                s  += statsIn[t * SLOT8 + k2];
                s2 += statsIn[SQOFF + t * SLOT8 + k2];
            }
            double inv = 1.0 / (double)N;
            float mean = (float)(s * inv);
            float var  = (float)(s2 * inv) - mean * mean;
            float sc   = rsqrtf(var + EPSB) * gamma[t];
            sc_s[t] = sc;
            sh_s[t] = beta[t] - mean * sc;
        }
    } else {
        if (t < 128) { int node = nbase + t; xs_s[t] = (node < N) ? x[node] * DH : 0; }
    }
    __syncthreads();

    // ---- fused gather into agg_s ----
    {
        const float4* src4 = reinterpret_cast<const float4*>(MODE == 1 ? emb : h);
        bool act = lane < A4;
#pragma unroll 1
        for (int i = 0; i < 16; ++i) {
            int ln = wid * 16 + i, node = nbase + ln;
            int s0 = 0, s1 = 0;
            if (node < N) { s0 = rowptr[node]; s1 = rowptr[node + 1]; }
            float4 acc = make_float4(0.f, 0.f, 0.f, 0.f);
            int e = s0;
            for (; e + 3 < s1; e += 4) {
                int c0 = colidx[e], c1 = colidx[e + 1];
                int c2 = colidx[e + 2], c3 = colidx[e + 3];
                int i0, i1, i2, i3;
                if (MODE == 1) { i0 = x[c0] * A4; i1 = x[c1] * A4; i2 = x[c2] * A4; i3 = x[c3] * A4; }
                else           { i0 = c0 * A4;    i1 = c1 * A4;    i2 = c2 * A4;    i3 = c3 * A4; }
                if (act) {
                    float4 v0 = src4[i0 + lane], v1 = src4[i1 + lane];
                    float4 v2 = src4[i2 + lane], v3 = src4[i3 + lane];
                    acc.x += (v0.x + v1.x) + (v2.x + v3.x);
                    acc.y += (v0.y + v1.y) + (v2.y + v3.y);
                    acc.z += (v0.z + v1.z) + (v2.z + v3.z);
                    acc.w += (v0.w + v1.w) + (v2.w + v3.w);
                }
            }
            for (; e < s1; ++e) {
                int c0 = colidx[e];
                int i0 = (MODE == 1) ? x[c0] * A4 : c0 * A4;
                if (act) {
                    float4 v = src4[i0 + lane];
                    acc.x += v.x; acc.y += v.y; acc.z += v.z; acc.w += v.w;
                }
            }
            if (act) {
                float4 r = acc;
                if (MODE == 2) {
                    float deg = (float)(s1 - s0);
                    float4 sc = reinterpret_cast<const float4*>(sc_s)[lane];
                    float4 sh = reinterpret_cast<const float4*>(sh_s)[lane];
                    r.x = fmaf(acc.x, sc.x, deg * sh.x);
                    r.y = fmaf(acc.y, sc.y, deg * sh.y);
                    r.z = fmaf(acc.z, sc.z, deg * sh.z);
                    r.w = fmaf(acc.w, sc.w, deg * sh.w);
                }
                reinterpret_cast<float4*>(agg_s)[ln * A4 + lane] = r;
            }
        }
    }
    __syncthreads();

    // ---- K-loop: stage z (from smem agg + global h-half) & W, run mma ----
    float4 acc[2][NT];
#pragma unroll
    for (int mt = 0; mt < 2; ++mt)
#pragma unroll
        for (int nt = 0; nt < NT; ++nt) acc[mt][nt] = make_float4(0.f, 0.f, 0.f, 0.f);

    for (int c = 0; c < NK; ++c) {
#pragma unroll
        for (int r = 0; r < 16; ++r) {
            int idx = t + r * 256;
            int kk = idx & 31, n = idx >> 5;
            int node = nbase + n;
            int k = c * 32 + kk;
            float v = 0.f;
            if (k < DAGG) {
                v = agg_s[n * DAGG + k];
            } else if (node < N) {
                if (MODE == 1) v = emb[xs_s[n] + (k - DAGG)];
                else {
                    float hv = h[(size_t)node * DH + (k - DAGG)];
                    v = fmaf(hv, sc_s[k - DAGG], sh_s[k - DAGG]);
                }
            }
            int np = (n & 0x70) | ((n & 7) << 1) | ((n >> 3) & 1);
            z_s[kk * ZS + np] = tf32cvt(v);
        }
#pragma unroll
        for (int idx = t; idx < 32 * MCHUNK; idx += 256) {
            int kk = idx & 31, j = idx >> 5;
            float wv = W[(size_t)(cbase + j) * K + c * 32 + kk];
            int kp = (kk & ~7) | ((kk & 3) << 1) | ((kk & 4) >> 2);
            w_s[j * WS + kp] = tf32cvt(wv);
        }
        __syncthreads();

#pragma unroll
        for (int g = 0; g < 4; ++g) {
            uint2 a01[2], a23[2];
#pragma unroll
            for (int mt = 0; mt < 2; ++mt) {
                int col = wm * 32 + mt * 16 + 2 * gr;
                a01[mt] = *reinterpret_cast<const uint2*>(&z_s[(g * 8 + tc) * ZS + col]);
                a23[mt] = *reinterpret_cast<const uint2*>(&z_s[(g * 8 + tc + 4) * ZS + col]);
            }
#pragma unroll
            for (int nt = 0; nt < NT; ++nt) {
                uint2 b = *reinterpret_cast<const uint2*>(
                    &w_s[(wn * NSPAN + nt * 8 + gr) * WS + g * 8 + tc * 2]);
                mma_tf32(acc[0][nt], a01[0], a23[0], b);
                mma_tf32(acc[1][nt], a01[1], a23[1], b);
            }
        }
        __syncthreads();
    }

    // ---- epilogue: bias + relu + store + BN stats ----
    const int slot = blockIdx.x & (SLOT8 - 1);
#pragma unroll
    for (int nt = 0; nt < NT; ++nt) {
        int col = cbase + wn * NSPAN + nt * 8 + 2 * tc;
        float b0 = bias[col], b1 = bias[col + 1];
        float s0 = 0.f, s1 = 0.f, q0 = 0.f, q1 = 0.f;
#pragma unroll
        for (int mt = 0; mt < 2; ++mt) {
            int node0 = nbase + wm * 32 + mt * 16 + gr;
            int node1 = node0 + 8;
            float4 a = acc[mt][nt];
            float r00 = fmaxf(a.x + b0, 0.f);
            float r01 = fmaxf(a.y + b1, 0.f);
            float r10 = fmaxf(a.z + b0, 0.f);
            float r11 = fmaxf(a.w + b1, 0.f);
            if (node0 < N) {
                *reinterpret_cast<float2*>(&out[(size_t)node0 * MTOT + col]) =
                    make_float2(r00, r01);
                s0 += r00; q0 += r00 * r00;
                s1 += r01; q1 += r01 * r01;
            }
            if (node1 < N) {
                *reinterpret_cast<float2*>(&out[(size_t)node1 * MTOT + col]) =
                    make_float2(r10, r11);
                s0 += r10; q0 += r10 * r10;
                s1 += r11; q1 += r11 * r11;
            }
        }
#pragma unroll
        for (int off = 4; off < 32; off <<= 1) {
            s0 += __shfl_xor_sync(0xffffffffu, s0, off);
            s1 += __shfl_xor_sync(0xffffffffu, s1, off);
            q0 += __shfl_xor_sync(0xffffffffu, q0, off);
            q1 += __shfl_xor_sync(0xffffffffu, q1, off);
        }
        if (gr == 0) {
            atomicAdd(&statsOut[col * SLOT8 + slot], (double)s0);
            atomicAdd(&statsOut[(col + 1) * SLOT8 + slot], (double)s1);
            atomicAdd(&statsOut[SQOFF + col * SLOT8 + slot], (double)q0);
            atomicAdd(&statsOut[SQOFF + (col + 1) * SLOT8 + slot], (double)q1);
        }
    }
}

// ---------------- plain TF32 GEMM (layer 3, reads agg from global) ----------------
template <int K, int DAGG, int DH, int MTOT, int MCHUNK>
__global__ void __launch_bounds__(256)
k_gemm_tc(const float* __restrict__ agg, const float* __restrict__ h,
          const float* __restrict__ W, const float* __restrict__ bias,
          float* __restrict__ out, int N) {
    constexpr int NK = K / 32, NSPAN = MCHUNK / 2, NT = NSPAN / 8;
    constexpr int ZS = 136, WS = 40;
    __shared__ unsigned z_s[32 * ZS];
    __shared__ unsigned w_s[MCHUNK * WS];

    const int t = threadIdx.x, lane = t & 31, wid = t >> 5;
    const int wm = wid & 3, wn = wid >> 2, gr = lane >> 2, tc = lane & 3;
    const int nbase = blockIdx.x * 128, cbase = blockIdx.y * MCHUNK;

    float4 acc[2][NT];
#pragma unroll
    for (int mt = 0; mt < 2; ++mt)
#pragma unroll
        for (int nt = 0; nt < NT; ++nt) acc[mt][nt] = make_float4(0.f, 0.f, 0.f, 0.f);

    for (int c = 0; c < NK; ++c) {
#pragma unroll
        for (int r = 0; r < 16; ++r) {
            int idx = t + r * 256;
            int kk = idx & 31, n = idx >> 5;
            int node = nbase + n;
            int k = c * 32 + kk;
            float v = 0.f;
            if (node < N)
                v = (k < DAGG) ? agg[(size_t)node * DAGG + k]
                               : h[(size_t)node * DH + (k - DAGG)];
            int np = (n & 0x70) | ((n & 7) << 1) | ((n >> 3) & 1);
            z_s[kk * ZS + np] = tf32cvt(v);
        }
#pragma unroll
        for (int idx = t; idx < 32 * MCHUNK; idx += 256) {
            int kk = idx & 31, j = idx >> 5;
            float wv = W[(size_t)(cbase + j) * K + c * 32 + kk];
            int kp = (kk & ~7) | ((kk & 3) << 1) | ((kk & 4) >> 2);
            w_s[j * WS + kp] = tf32cvt(wv);
        }
        __syncthreads();

#pragma unroll
        for (int g = 0; g < 4; ++g) {
            uint2 a01[2], a23[2];
#pragma unroll
            for (int mt = 0; mt < 2; ++mt) {
                int col = wm * 32 + mt * 16 + 2 * gr;
                a01[mt] = *reinterpret_cast<const uint2*>(&z_s[(g * 8 + tc) * ZS + col]);
                a23[mt] = *reinterpret_cast<const uint2*>(&z_s[(g * 8 + tc + 4) * ZS + col]);
            }
#pragma unroll
            for (int nt = 0; nt < NT; ++nt) {
                uint2 b = *reinterpret_cast<const uint2*>(
                    &w_s[(wn * NSPAN + nt * 8 + gr) * WS + g * 8 + tc * 2]);
                mma_tf32(acc[0][nt], a01[0], a23[0], b);
                mma_tf32(acc[1][nt], a01[1], a23[1], b);
            }
        }
        __syncthreads();
    }

#pragma unroll
    for (int nt = 0; nt < NT; ++nt) {
        int col = cbase + wn * NSPAN + nt * 8 + 2 * tc;
        float b0 = bias[col], b1 = bias[col + 1];
#pragma unroll
        for (int mt = 0; mt < 2; ++mt) {
            int node0 = nbase + wm * 32 + mt * 16 + gr;
            int node1 = node0 + 8;
            float4 a = acc[mt][nt];
            if (node0 < N)
                *reinterpret_cast<float2*>(&out[(size_t)node0 * MTOT + col]) =
                    make_float2(fmaxf(a.x + b0, 0.f), fmaxf(a.y + b1, 0.f));
            if (node1 < N)
                *reinterpret_cast<float2*>(&out[(size_t)node1 * MTOT + col]) =
                    make_float2(fmaxf(a.z + b0, 0.f), fmaxf(a.w + b1, 0.f));
        }
    }
}

// BN finalize (layer 2, for the pool)
__global__ void k_bnfin(const double* __restrict__ stats, const float* __restrict__ g,
                        const float* __restrict__ be, float* __restrict__ scale,
                        float* __restrict__ shift, int M, int N) {
    int j = blockIdx.x * blockDim.x + threadIdx.x;
    if (j < M) {
        double s = 0.0, s2 = 0.0;
#pragma unroll
        for (int k = 0; k < SLOT8; ++k) {
            s  += stats[j * SLOT8 + k];
            s2 += stats[SQOFF + j * SLOT8 + k];
        }
        double inv = 1.0 / (double)N;
        float mean = (float)(s * inv);
        float var  = (float)(s2 * inv) - mean * mean;
        float sc   = rsqrtf(var + EPSB) * g[j];
        scale[j] = sc;
        shift[j] = be[j] - mean * sc;
    }
}

// ---------------- launch ----------------
static inline int cdiv(int a, int b) { return (a + b - 1) / b; }

extern "C" void kernel_launch(void* const* d_in, const int* in_sizes, int n_in,
                              void* d_out, int out_size) {
    (void)in_sizes; (void)n_in; (void)out_size;
    const int*   x       = (const int*)d_in[0];
    const int*   ei      = (const int*)d_in[1];
    const int*   batch   = (const int*)d_in[2];
    const int*   cluster = (const int*)d_in[3];
    const int*   gei     = (const int*)d_in[4];
    const float* emb     = (const float*)d_in[5];
    const float* w1      = (const float*)d_in[6];
    const float* b1      = (const float*)d_in[7];
    const float* g1      = (const float*)d_in[8];
    const float* be1     = (const float*)d_in[9];
    const float* w2      = (const float*)d_in[10];
    const float* b2      = (const float*)d_in[11];
    const float* g2      = (const float*)d_in[12];
    const float* be2     = (const float*)d_in[13];
    const float* wm      = (const float*)d_in[14];
    const float* bm      = (const float*)d_in[15];
    float* out = (float*)d_out;

    float *agg, *h1, *h2, *y, *y2, *scale, *shift;
    unsigned char* zb;
    int *rowptr, *cur, *colidx;
    int *nstart, *gstart, *ybatch, *psum;
    cudaGetSymbolAddress((void**)&agg,     g_agg);
    cudaGetSymbolAddress((void**)&h1,      g_h1);
    cudaGetSymbolAddress((void**)&h2,      g_h2);
    cudaGetSymbolAddress((void**)&y,       g_y);
    cudaGetSymbolAddress((void**)&y2,      g_y2);
    cudaGetSymbolAddress((void**)&zb,      g_zerobuf);
    cudaGetSymbolAddress((void**)&rowptr,  g_rowptr);
    cudaGetSymbolAddress((void**)&cur,     g_cur);
    cudaGetSymbolAddress((void**)&colidx,  g_colidx);
    cudaGetSymbolAddress((void**)&nstart,  g_nstart);
    cudaGetSymbolAddress((void**)&gstart,  g_gstart);
    cudaGetSymbolAddress((void**)&ybatch,  g_ybatch);
    cudaGetSymbolAddress((void**)&psum,    g_psum);
    cudaGetSymbolAddress((void**)&scale,   g_scale);
    cudaGetSymbolAddress((void**)&shift,   g_shift);

    int* cnt = (int*)zb;
    double* stats = (double*)(zb + CNT_BYTES);

    const int T = 256;
    const int SM1 = 32 * 136 * 4 + 80 * 40 * 4 + 128 * 64 * 4 + 512;      // 63488
    const int SM2 = 32 * 136 * 4 + 96 * 40 * 4 + 128 * 80 * 4 + 2 * 80 * 4; // 74368
    cudaFuncSetAttribute(k_gemm_fused<128, 64, 64, 80, 80, 1>,
                         cudaFuncAttributeMaxDynamicSharedMemorySize, SM1);
    cudaFuncSetAttribute(k_gemm_fused<160, 80, 80, 96, 96, 2>,
                         cudaFuncAttributeMaxDynamicSharedMemorySize, SM2);

    // ---- zero counters + stats in ONE memset ----
    cudaMemsetAsync(zb, 0, ZERO_BYTES);

    // ---- combined CSR build ----
    k_hist<<<cdiv(NEALL, T), T>>>(ei, gei, cnt);
    k_scan1<<<cdiv(NSEG, 1024), 256>>>(cnt, rowptr, psum, NSEG);
    k_scan3f<<<cdiv(NSEG, T), T>>>(rowptr, cur, psum, NSEG, NEALL, cdiv(NSEG, 1024));
    k_ticket_bound<<<TBLK + cdiv(NN, T), T>>>(ei, gei, cur, colidx, cluster, nstart);

    // ---- layer 1: fused gather + conv(64 -> 80), stats0 ----
    k_gemm_fused<128, 64, 64, 80, 80, 1><<<cdiv(NN, 128), T, SM1>>>(
        rowptr, colidx, x, emb, nullptr, nullptr, nullptr, nullptr,
        w1, b1, h1, NN, stats);

    // ---- layer 2: fused BN1-finalize + gather + conv(80 -> 96), stats1 ----
    k_gemm_fused<160, 80, 80, 96, 96, 2><<<cdiv(NN, 128), T, SM2>>>(
        rowptr, colidx, nullptr, nullptr, h1, stats, g1, be1,
        w2, b2, h2, NN, stats + LSTRIDE);
    k_bnfin<<<1, 128>>>(stats + LSTRIDE, g2, be2, scale, shift, 96, NN);

    // ---- cluster max-pool with BN2 fold + ybatch ----
    k_pool<<<NC, 128>>>(h2, nstart, batch, scale, shift, y, ybatch);
    k_bound<<<cdiv(NC, T), T>>>(ybatch, NC, NG, gstart);

    // ---- global conv(96 -> 256) ----
    k_gather96<<<cdiv(NC * 32, T), T>>>(rowptr + NN, colidx, y, agg, NC);
    k_gemm_tc<192, 96, 96, 256, 128><<<dim3(cdiv(NC, 128), 2), T>>>(
        agg, y, wm, bm, y2, NC);

    // ---- graph max-pool -> output ----
    k_final<<<NG, 256>>>(y2, gstart, out);
}

// round 9
// speedup vs baseline: 1.0251x; 1.0251x over previous
#include <cuda_runtime.h>
#include <cfloat>
#include <math.h>

// ---------------- problem constants ----------------
#define NN   100000   // nodes
#define NE   800000   // edges
#define NC   20000    // clusters
#define NGE  320000   // global edges
#define NG   256      // graphs
#define EPSB 1e-5f
#define NSEG (NN + NC)
#define NEALL (NE + NGE)
#define SLOT8 8
#define SQOFF (256 * SLOT8)
#define LSTRIDE (512 * SLOT8)
#define CNT_BYTES (NSEG * 4)
#define ZERO_BYTES (CNT_BYTES + 2 * LSTRIDE * 8)
#define TBLK 4375                    // NEALL/256 exactly

// ---------------- scratch (device globals) ----------------
__device__ __align__(16) float  g_agg[NN * 96];
__device__ __align__(16) float  g_h1[NN * 80];
__device__ __align__(16) float  g_h2[NN * 96];
__device__ __align__(16) float  g_y [NC * 96];
__device__ __align__(16) float  g_y2[NC * 256];
__device__ __align__(16) unsigned char g_zerobuf[ZERO_BYTES];   // [cnt | stats]
__device__ __align__(16) int    g_rowptr[NSEG + 1];
__device__ __align__(16) int    g_rank[NEALL];
__device__ __align__(16) int    g_colidx[NEALL];
__device__ int    g_nstart[NC + 1];
__device__ int    g_gstart[NG + 1];
__device__ int    g_ybatch[NC];
__device__ int    g_psum[128];
__device__ __align__(16) float  g_scale[256];
__device__ __align__(16) float  g_shift[256];

// ---------------- tf32 / mma helpers ----------------
__device__ __forceinline__ unsigned tf32cvt(float f) {
    unsigned u;
    asm("cvt.rna.tf32.f32 %0, %1;" : "=r"(u) : "f"(f));
    return u;
}
__device__ __forceinline__ void mma_tf32(float4& d, uint2 a01, uint2 a23, uint2 b) {
    asm volatile(
        "mma.sync.aligned.m16n8k8.row.col.f32.tf32.tf32.f32 "
        "{%0,%1,%2,%3}, {%4,%5,%6,%7}, {%8,%9}, {%0,%1,%2,%3};"
        : "+f"(d.x), "+f"(d.y), "+f"(d.z), "+f"(d.w)
        : "r"(a01.x), "r"(a01.y), "r"(a23.x), "r"(a23.y), "r"(b.x), "r"(b.y));
}

// ---------------- CSR build: hist(+rank) -> scan -> atomic-free ticket ----------------
__global__ void k_hist(const int* __restrict__ ei, const int* __restrict__ gei,
                       int* __restrict__ cnt, int* __restrict__ rank) {
    int i = blockIdx.x * blockDim.x + threadIdx.x;
    if (i < NE) {
        rank[i] = atomicAdd(&cnt[ei[NE + i]], 1);
    } else if (i < NEALL) {
        int e = i - NE;
        rank[i] = atomicAdd(&cnt[NN + gei[NGE + e]], 1);
    }
}

__global__ void k_scan1(const int* __restrict__ cnt, int* __restrict__ loc,
                        int* __restrict__ psum, int n) {
    __shared__ int sh[256];
    int t = threadIdx.x;
    int idx = blockIdx.x * 1024 + t * 4;
    int a0 = 0, a1 = 0, a2 = 0, a3 = 0;
    if (idx + 3 < n) {
        int4 q = *reinterpret_cast<const int4*>(cnt + idx);
        a0 = q.x; a1 = q.y; a2 = q.z; a3 = q.w;
    } else {
        if (idx     < n) a0 = cnt[idx];
        if (idx + 1 < n) a1 = cnt[idx + 1];
        if (idx + 2 < n) a2 = cnt[idx + 2];
    }
    int s = a0 + a1 + a2 + a3;
    sh[t] = s; __syncthreads();
    for (int off = 1; off < 256; off <<= 1) {
        int u = (t >= off) ? sh[t - off] : 0;
        __syncthreads(); sh[t] += u; __syncthreads();
    }
    int excl = sh[t] - s;
    if (idx     < n) loc[idx]     = excl;
    if (idx + 1 < n) loc[idx + 1] = excl + a0;
    if (idx + 2 < n) loc[idx + 2] = excl + a0 + a1;
    if (idx + 3 < n) loc[idx + 3] = excl + a0 + a1 + a2;
    if (t == 255) psum[blockIdx.x] = sh[t];
}

// scan3 with embedded top-level scan of psum (each block redundantly scans)
__global__ void k_scan3f(int* __restrict__ rowptr, const int* __restrict__ psum,
                         int n, int total, int nb) {
    __shared__ int sh[128];
    __shared__ int excl[128];
    int t = threadIdx.x;
    int v = 0;
    if (t < 128) { v = (t < nb) ? psum[t] : 0; sh[t] = v; }
    __syncthreads();
    for (int off = 1; off < 128; off <<= 1) {
        int u = 0;
        if (t < 128 && t >= off) u = sh[t - off];
        __syncthreads();
        if (t < 128) sh[t] += u;
        __syncthreads();
    }
    if (t < 128) excl[t] = sh[t] - v;
    __syncthreads();
    int i = blockIdx.x * blockDim.x + t;
    if (i < n) rowptr[i] += excl[i >> 10];
    if (i == 0) rowptr[n] = total;
}

// atomic-free ticket (rowptr[d] + rank) + fused cluster segment boundaries
__global__ void k_ticket_bound(const int* __restrict__ ei, const int* __restrict__ gei,
                               const int* __restrict__ rowptr, const int* __restrict__ rank,
                               int* __restrict__ colidx,
                               const int* __restrict__ cluster, int* __restrict__ nstart) {
    int b = blockIdx.x, t = threadIdx.x;
    if (b < TBLK) {
        int i = b * 256 + t;
        if (i < NE) {
            colidx[rowptr[ei[NE + i]] + rank[i]] = ei[i];
        } else if (i < NEALL) {
            int e = i - NE;
            colidx[rowptr[NN + gei[NGE + e]] + rank[i]] = gei[e];
        }
    } else {
        int i = (b - TBLK) * 256 + t;
        if (i == 0) { nstart[0] = 0; nstart[NC] = NN; }
        else if (i < NN) {
            int c0 = cluster[i - 1], c1 = cluster[i];
            for (int c = c0 + 1; c <= c1; ++c) nstart[c] = i;
        }
    }
}

// ---------------- gather aggregations (float4 rows, unroll x4) ----------------
__global__ void k_gather_emb(const int* __restrict__ rowptr, const int* __restrict__ colidx,
                             const int* __restrict__ x, const float* __restrict__ emb,
                             float* __restrict__ agg) {
    int gid = blockIdx.x * blockDim.x + threadIdx.x;
    int w = gid >> 4;
    int lane = threadIdx.x & 15;
    if (w >= NN) return;
    int s0 = rowptr[w], s1 = rowptr[w + 1];
    const float4* e4 = reinterpret_cast<const float4*>(emb);
    float4 acc = make_float4(0.f, 0.f, 0.f, 0.f);
    int e = s0;
    for (; e + 3 < s1; e += 4) {
        int i0 = x[colidx[e]] * 16,     i1 = x[colidx[e + 1]] * 16;
        int i2 = x[colidx[e + 2]] * 16, i3 = x[colidx[e + 3]] * 16;
        float4 v0 = e4[i0 + lane], v1 = e4[i1 + lane];
        float4 v2 = e4[i2 + lane], v3 = e4[i3 + lane];
        acc.x += (v0.x + v1.x) + (v2.x + v3.x);
        acc.y += (v0.y + v1.y) + (v2.y + v3.y);
        acc.z += (v0.z + v1.z) + (v2.z + v3.z);
        acc.w += (v0.w + v1.w) + (v2.w + v3.w);
    }
    for (; e < s1; ++e) {
        float4 v = e4[x[colidx[e]] * 16 + lane];
        acc.x += v.x; acc.y += v.y; acc.z += v.z; acc.w += v.w;
    }
    reinterpret_cast<float4*>(agg)[w * 16 + lane] = acc;
}

__global__ void k_gather_bn80(const int* __restrict__ rowptr, const int* __restrict__ colidx,
                              const float* __restrict__ h1, const float* __restrict__ scale,
                              const float* __restrict__ shift, float* __restrict__ agg) {
    int w = (blockIdx.x * blockDim.x + threadIdx.x) >> 5;
    int lane = threadIdx.x & 31;
    if (w >= NN) return;
    int s0 = rowptr[w], s1 = rowptr[w + 1];
    const float4* h4 = reinterpret_cast<const float4*>(h1);
    float4 acc = make_float4(0.f, 0.f, 0.f, 0.f);
    bool act = lane < 20;
    int e = s0;
    for (; e + 3 < s1; e += 4) {
        int i0 = colidx[e] * 20,     i1 = colidx[e + 1] * 20;
        int i2 = colidx[e + 2] * 20, i3 = colidx[e + 3] * 20;
        if (act) {
            float4 v0 = h4[i0 + lane], v1 = h4[i1 + lane];
            float4 v2 = h4[i2 + lane], v3 = h4[i3 + lane];
            acc.x += (v0.x + v1.x) + (v2.x + v3.x);
            acc.y += (v0.y + v1.y) + (v2.y + v3.y);
            acc.z += (v0.z + v1.z) + (v2.z + v3.z);
            acc.w += (v0.w + v1.w) + (v2.w + v3.w);
        }
    }
    for (; e < s1; ++e) {
        if (act) {
            float4 v = h4[colidx[e] * 20 + lane];
            acc.x += v.x; acc.y += v.y; acc.z += v.z; acc.w += v.w;
        }
    }
    if (act) {
        float deg = (float)(s1 - s0);
        float4 sc = reinterpret_cast<const float4*>(scale)[lane];
        float4 sh = reinterpret_cast<const float4*>(shift)[lane];
        float4 r;
        r.x = fmaf(acc.x, sc.x, deg * sh.x);
        r.y = fmaf(acc.y, sc.y, deg * sh.y);
        r.z = fmaf(acc.z, sc.z, deg * sh.z);
        r.w = fmaf(acc.w, sc.w, deg * sh.w);
        reinterpret_cast<float4*>(agg)[w * 20 + lane] = r;
    }
}

__global__ void k_gather96(const int* __restrict__ rowptr, const int* __restrict__ colidx,
                           const float* __restrict__ src, float* __restrict__ agg, int N) {
    int w = (blockIdx.x * blockDim.x + threadIdx.x) >> 5;
    int lane = threadIdx.x & 31;
    if (w >= N) return;
    int s0 = rowptr[w], s1 = rowptr[w + 1];
    const float4* s4 = reinterpret_cast<const float4*>(src);
    float4 acc = make_float4(0.f, 0.f, 0.f, 0.f);
    bool act = lane < 24;
    int e = s0;
    for (; e + 3 < s1; e += 4) {
        int i0 = colidx[e] * 24,     i1 = colidx[e + 1] * 24;
        int i2 = colidx[e + 2] * 24, i3 = colidx[e + 3] * 24;
        if (act) {
            float4 v0 = s4[i0 + lane], v1 = s4[i1 + lane];
            float4 v2 = s4[i2 + lane], v3 = s4[i3 + lane];
            acc.x += (v0.x + v1.x) + (v2.x + v3.x);
            acc.y += (v0.y + v1.y) + (v2.y + v3.y);
            acc.z += (v0.z + v1.z) + (v2.z + v3.z);
            acc.w += (v0.w + v1.w) + (v2.w + v3.w);
        }
    }
    for (; e < s1; ++e) {
        if (act) {
            float4 v = s4[colidx[e] * 24 + lane];
            acc.x += v.x; acc.y += v.y; acc.z += v.z; acc.w += v.w;
        }
    }
    if (act) reinterpret_cast<float4*>(agg)[w * 24 + lane] = acc;
}

// ---------------- segment boundaries (sorted ids) ----------------
__global__ void k_bound(const int* __restrict__ seg, int n, int nseg,
                        int* __restrict__ start) {
    int i = blockIdx.x * blockDim.x + threadIdx.x;
    if (i == 0) { start[0] = 0; start[nseg] = n; }
    else if (i < n) {
        int c0 = seg[i - 1], c1 = seg[i];
        for (int c = c0 + 1; c <= c1; ++c) start[c] = i;
    }
}

// cluster pool with BN2 fold (sign-safe)
__global__ void __launch_bounds__(128)
k_pool(const float* __restrict__ h2, const int* __restrict__ nstart,
       const int* __restrict__ batch, const float* __restrict__ scale,
       const float* __restrict__ shift, float* __restrict__ y, int* __restrict__ ybatch) {
    int c = blockIdx.x;
    int t = threadIdx.x;
    int ns = nstart[c], ne = nstart[c + 1];
    if (t < 96) {
        float mx = -FLT_MAX, mn = FLT_MAX;
        for (int n = ns; n < ne; ++n) {
            float v = h2[(size_t)n * 96 + t];
            mx = fmaxf(mx, v); mn = fminf(mn, v);
        }
        float sc = scale[t];
        y[(size_t)c * 96 + t] = fmaf(sc >= 0.f ? mx : mn, sc, shift[t]);
    } else if (t == 96 && ne > ns) {
        ybatch[c] = batch[ne - 1];
    }
}

__global__ void __launch_bounds__(256)
k_final(const float* __restrict__ y2, const int* __restrict__ gstart,
        float* __restrict__ out) {
    int g = blockIdx.x;
    int f = threadIdx.x;
    int gs = gstart[g], ge = gstart[g + 1];
    float mx = -FLT_MAX;
    for (int c = gs; c < ge; ++c)
        mx = fmaxf(mx, y2[(size_t)c * 256 + f]);
    out[(size_t)g * 256 + f] = mx;
}

// ---------------- TF32 tensor-core GEMM (+relu, +BN stats) ----------------
template <int K, int DAGG, int DH, int MTOT, int MCHUNK, bool STATS, bool BNZ, bool EMB>
__global__ void __launch_bounds__(256)
k_gemm_tc(const float* __restrict__ agg, const float* __restrict__ h,
          const int* __restrict__ x, const float* __restrict__ emb,
          const float* __restrict__ W, const float* __restrict__ bias,
          float* __restrict__ out, int N, double* __restrict__ stats,
          const float* __restrict__ zsc, const float* __restrict__ zsh) {
    constexpr int NK = K / 32, NSPAN = MCHUNK / 2, NT = NSPAN / 8;
    constexpr int ZS = 136, WS = 40;
    __shared__ unsigned z_s[32 * ZS];
    __shared__ unsigned w_s[MCHUNK * WS];

    const int t = threadIdx.x, lane = t & 31, wid = t >> 5;
    const int wm = wid & 3, wn = wid >> 2, gr = lane >> 2, tc = lane & 3;
    const int nbase = blockIdx.x * 128, cbase = blockIdx.y * MCHUNK;

    float4 acc[2][NT];
#pragma unroll
    for (int mt = 0; mt < 2; ++mt)
#pragma unroll
        for (int nt = 0; nt < NT; ++nt) acc[mt][nt] = make_float4(0.f, 0.f, 0.f, 0.f);

    for (int c = 0; c < NK; ++c) {
#pragma unroll
        for (int r = 0; r < 16; ++r) {
            int idx = t + r * 256;
            int kk = idx & 31, n = idx >> 5;
            int node = nbase + n;
            int k = c * 32 + kk;
            float v = 0.f;
            if (node < N) {
                if (k < DAGG) v = agg[(size_t)node * DAGG + k];
                else if (EMB) v = emb[x[node] * DH + (k - DAGG)];
                else {
                    float hv = h[(size_t)node * DH + (k - DAGG)];
                    v = BNZ ? fmaf(hv, zsc[k - DAGG], zsh[k - DAGG]) : hv;
                }
            }
            int np = (n & 0x70) | ((n & 7) << 1) | ((n >> 3) & 1);
            z_s[kk * ZS + np] = tf32cvt(v);
        }
#pragma unroll
        for (int idx = t; idx < 32 * MCHUNK; idx += 256) {
            int kk = idx & 31, j = idx >> 5;
            float wv = W[(size_t)(cbase + j) * K + c * 32 + kk];
            int kp = (kk & ~7) | ((kk & 3) << 1) | ((kk & 4) >> 2);
            w_s[j * WS + kp] = tf32cvt(wv);
        }
        __syncthreads();

#pragma unroll
        for (int g = 0; g < 4; ++g) {
            uint2 a01[2], a23[2];
#pragma unroll
            for (int mt = 0; mt < 2; ++mt) {
                int col = wm * 32 + mt * 16 + 2 * gr;
                a01[mt] = *reinterpret_cast<const uint2*>(&z_s[(g * 8 + tc) * ZS + col]);
                a23[mt] = *reinterpret_cast<const uint2*>(&z_s[(g * 8 + tc + 4) * ZS + col]);
            }
#pragma unroll
            for (int nt = 0; nt < NT; ++nt) {
                uint2 b = *reinterpret_cast<const uint2*>(
                    &w_s[(wn * NSPAN + nt * 8 + gr) * WS + g * 8 + tc * 2]);
                mma_tf32(acc[0][nt], a01[0], a23[0], b);
                mma_tf32(acc[1][nt], a01[1], a23[1], b);
            }
        }
        __syncthreads();
    }

    const int slot = blockIdx.x & (SLOT8 - 1);
#pragma unroll
    for (int nt = 0; nt < NT; ++nt) {
        int col = cbase + wn * NSPAN + nt * 8 + 2 * tc;
        float b0 = bias[col], b1 = bias[col + 1];
        float s0 = 0.f, s1 = 0.f, q0 = 0.f, q1 = 0.f;
#pragma unroll
        for (int mt = 0; mt < 2; ++mt) {
            int node0 = nbase + wm * 32 + mt * 16 + gr;
            int node1 = node0 + 8;
            float4 a = acc[mt][nt];
            float r00 = fmaxf(a.x + b0, 0.f);
            float r01 = fmaxf(a.y + b1, 0.f);
            float r10 = fmaxf(a.z + b0, 0.f);
            float r11 = fmaxf(a.w + b1, 0.f);
            if (node0 < N) {
                *reinterpret_cast<float2*>(&out[(size_t)node0 * MTOT + col]) =
                    make_float2(r00, r01);
                s0 += r00; q0 += r00 * r00;
                s1 += r01; q1 += r01 * r01;
            }
            if (node1 < N) {
                *reinterpret_cast<float2*>(&out[(size_t)node1 * MTOT + col]) =
                    make_float2(r10, r11);
                s0 += r10; q0 += r10 * r10;
                s1 += r11; q1 += r11 * r11;
            }
        }
        if (STATS) {
#pragma unroll
            for (int off = 4; off < 32; off <<= 1) {
                s0 += __shfl_xor_sync(0xffffffffu, s0, off);
                s1 += __shfl_xor_sync(0xffffffffu, s1, off);
                q0 += __shfl_xor_sync(0xffffffffu, q0, off);
                q1 += __shfl_xor_sync(0xffffffffu, q1, off);
            }
            if (gr == 0) {
                atomicAdd(&stats[col * SLOT8 + slot], (double)s0);
                atomicAdd(&stats[(col + 1) * SLOT8 + slot], (double)s1);
                atomicAdd(&stats[SQOFF + col * SLOT8 + slot], (double)q0);
                atomicAdd(&stats[SQOFF + (col + 1) * SLOT8 + slot], (double)q1);
            }
        }
    }
}

// BN finalize: reduce 8 slots, biased variance
__global__ void k_bnfin(const double* __restrict__ stats, const float* __restrict__ g,
                        const float* __restrict__ be, float* __restrict__ scale,
                        float* __restrict__ shift, int M, int N) {
    int j = blockIdx.x * blockDim.x + threadIdx.x;
    if (j < M) {
        double s = 0.0, s2 = 0.0;
#pragma unroll
        for (int k = 0; k < SLOT8; ++k) {
            s  += stats[j * SLOT8 + k];
            s2 += stats[SQOFF + j * SLOT8 + k];
        }
        double inv = 1.0 / (double)N;
        float mean = (float)(s * inv);
        float var  = (float)(s2 * inv) - mean * mean;
        float sc   = rsqrtf(var + EPSB) * g[j];
        scale[j] = sc;
        shift[j] = be[j] - mean * sc;
    }
}

// ---------------- launch ----------------
static inline int cdiv(int a, int b) { return (a + b - 1) / b; }

extern "C" void kernel_launch(void* const* d_in, const int* in_sizes, int n_in,
                              void* d_out, int out_size) {
    (void)in_sizes; (void)n_in; (void)out_size;
    const int*   x       = (const int*)d_in[0];
    const int*   ei      = (const int*)d_in[1];
    const int*   batch   = (const int*)d_in[2];
    const int*   cluster = (const int*)d_in[3];
    const int*   gei     = (const int*)d_in[4];
    const float* emb     = (const float*)d_in[5];
    const float* w1      = (const float*)d_in[6];
    const float* b1      = (const float*)d_in[7];
    const float* g1      = (const float*)d_in[8];
    const float* be1     = (const float*)d_in[9];
    const float* w2      = (const float*)d_in[10];
    const float* b2      = (const float*)d_in[11];
    const float* g2      = (const float*)d_in[12];
    const float* be2     = (const float*)d_in[13];
    const float* wm      = (const float*)d_in[14];
    const float* bm      = (const float*)d_in[15];
    float* out = (float*)d_out;

    float *agg, *h1, *h2, *y, *y2, *scale, *shift;
    unsigned char* zb;
    int *rowptr, *rank, *colidx;
    int *nstart, *gstart, *ybatch, *psum;
    cudaGetSymbolAddress((void**)&agg,     g_agg);
    cudaGetSymbolAddress((void**)&h1,      g_h1);
    cudaGetSymbolAddress((void**)&h2,      g_h2);
    cudaGetSymbolAddress((void**)&y,       g_y);
    cudaGetSymbolAddress((void**)&y2,      g_y2);
    cudaGetSymbolAddress((void**)&zb,      g_zerobuf);
    cudaGetSymbolAddress((void**)&rowptr,  g_rowptr);
    cudaGetSymbolAddress((void**)&rank,    g_rank);
    cudaGetSymbolAddress((void**)&colidx,  g_colidx);
    cudaGetSymbolAddress((void**)&nstart,  g_nstart);
    cudaGetSymbolAddress((void**)&gstart,  g_gstart);
    cudaGetSymbolAddress((void**)&ybatch,  g_ybatch);
    cudaGetSymbolAddress((void**)&psum,    g_psum);
    cudaGetSymbolAddress((void**)&scale,   g_scale);
    cudaGetSymbolAddress((void**)&shift,   g_shift);

    int* cnt = (int*)zb;
    double* stats = (double*)(zb + CNT_BYTES);

    const int T = 256;

    // ---- zero counters + stats in ONE memset ----
    cudaMemsetAsync(zb, 0, ZERO_BYTES);

    // ---- combined CSR build (nodes + clusters), atomic-free ticket ----
    k_hist<<<cdiv(NEALL, T), T>>>(ei, gei, cnt, rank);
    k_scan1<<<cdiv(NSEG, 1024), 256>>>(cnt, rowptr, psum, NSEG);
    k_scan3f<<<cdiv(NSEG, T), T>>>(rowptr, psum, NSEG, NEALL, cdiv(NSEG, 1024));
    k_ticket_bound<<<TBLK + cdiv(NN, T), T>>>(ei, gei, rowptr, rank, colidx,
                                              cluster, nstart);

    // ---- layer 1: gather + conv(64 -> 80), stats0 ----
    k_gather_emb<<<cdiv(NN * 16, T), T>>>(rowptr, colidx, x, emb, agg);
    k_gemm_tc<128, 64, 64, 80, 80, true, false, true><<<dim3(cdiv(NN, 128), 1), T>>>(
        agg, nullptr, x, emb, w1, b1, h1, NN, stats, nullptr, nullptr);
    k_bnfin<<<1, 128>>>(stats, g1, be1, scale, shift, 80, NN);

    // ---- layer 2: BN1-folded gather + conv(80 -> 96), stats1 ----
    k_gather_bn80<<<cdiv(NN * 32, T), T>>>(rowptr, colidx, h1, scale, shift, agg);
    k_gemm_tc<160, 80, 80, 96, 96, true, true, false><<<dim3(cdiv(NN, 128), 1), T>>>(
        agg, h1, nullptr, nullptr, w2, b2, h2, NN, stats + LSTRIDE, scale, shift);
    k_bnfin<<<1, 128>>>(stats + LSTRIDE, g2, be2, scale + 96, shift + 96, 96, NN);

    // ---- cluster max-pool with BN2 fold + ybatch ----
    k_pool<<<NC, 128>>>(h2, nstart, batch, scale + 96, shift + 96, y, ybatch);
    k_bound<<<cdiv(NC, T), T>>>(ybatch, NC, NG, gstart);

    // ---- global conv(96 -> 256) ----
    k_gather96<<<cdiv(NC * 32, T), T>>>(rowptr + NN, colidx, y, agg, NC);
    k_gemm_tc<192, 96, 96, 256, 128, false, false, false><<<dim3(cdiv(NC, 128), 2), T>>>(
        agg, y, nullptr, nullptr, wm, bm, y2, NC, nullptr, nullptr, nullptr);

    // ---- graph max-pool -> output ----
    k_final<<<NG, 256>>>(y2, gstart, out);
}